// round 1
// baseline (speedup 1.0000x reference)
#include <cuda_runtime.h>
#include <cuda_bf16.h>

#define N_USERS 50000
#define N_ITEMS 50000
#define NN      100000        // total nodes
#define EMBED   64
#define FDIM    192           // 3 streams interleaved: [e | img | txt]
#define NEDGES  1600000
#define BATCH   4096
#define CAT_RATE 0.02f

// ---------------- device scratch (allocation-free rule: __device__ globals) ----
__device__ float g_A[NN * FDIM];      // ping
__device__ float g_B[NN * FDIM];      // pong
__device__ float g_S[NN * FDIM];      // running sum over layers
__device__ int   g_count[NN];
__device__ int   g_rowstart[NN + 1];
__device__ int   g_cursor[NN];
__device__ int   g_ecol[NEDGES];
__device__ float g_eval[NEDGES];
__device__ int   g_blocksums[256];

// ---------------- CSR build ---------------------------------------------------
__global__ void k_zero_counts() {
    int i = blockIdx.x * blockDim.x + threadIdx.x;
    if (i < NN) g_count[i] = 0;
}

__global__ void k_hist(const int* __restrict__ rows) {
    int e = blockIdx.x * blockDim.x + threadIdx.x;
    if (e < NEDGES) atomicAdd(&g_count[rows[e]], 1);
}

#define SCAN_T 512
#define SCAN_NB ((NN + SCAN_T - 1) / SCAN_T)   // 196

__global__ void k_scan_p1() {   // per-block sums
    __shared__ int sm[SCAN_T];
    int i = blockIdx.x * SCAN_T + threadIdx.x;
    sm[threadIdx.x] = (i < NN) ? g_count[i] : 0;
    __syncthreads();
    for (int off = SCAN_T / 2; off > 0; off >>= 1) {
        if (threadIdx.x < off) sm[threadIdx.x] += sm[threadIdx.x + off];
        __syncthreads();
    }
    if (threadIdx.x == 0) g_blocksums[blockIdx.x] = sm[0];
}

__global__ void k_scan_p2() {   // exclusive scan of block sums (single thread ok: 196 elems)
    if (threadIdx.x == 0 && blockIdx.x == 0) {
        int run = 0;
        for (int b = 0; b < SCAN_NB; b++) {
            int v = g_blocksums[b];
            g_blocksums[b] = run;
            run += v;
        }
    }
}

__global__ void k_scan_p3() {   // exclusive scan within block + offset; fill rowstart & cursor
    __shared__ int sm[SCAN_T];
    int i = blockIdx.x * SCAN_T + threadIdx.x;
    int v = (i < NN) ? g_count[i] : 0;
    sm[threadIdx.x] = v;
    __syncthreads();
    // Hillis-Steele inclusive scan
    for (int off = 1; off < SCAN_T; off <<= 1) {
        int add = (threadIdx.x >= off) ? sm[threadIdx.x - off] : 0;
        __syncthreads();
        sm[threadIdx.x] += add;
        __syncthreads();
    }
    int excl = sm[threadIdx.x] - v + g_blocksums[blockIdx.x];
    if (i < NN) {
        g_rowstart[i] = excl;
        g_cursor[i]   = excl;
    }
    if (i == 0) g_rowstart[NN] = NEDGES;
}

__global__ void k_scatter(const int* __restrict__ rows, const int* __restrict__ cols,
                          const float* __restrict__ vals) {
    int e = blockIdx.x * blockDim.x + threadIdx.x;
    if (e < NEDGES) {
        int r = rows[e];
        int p = atomicAdd(&g_cursor[r], 1);
        g_ecol[p] = cols[e];
        g_eval[p] = vals[e];
    }
}

// ---------------- feature init ------------------------------------------------
// copy E0 (N,64) into plane 0 of A and S
__global__ void k_init_e(const float* __restrict__ E0) {
    int i = blockIdx.x * blockDim.x + threadIdx.x;   // over NN*64
    if (i < NN * EMBED) {
        int n = i >> 6, d = i & 63;
        float v = E0[i];
        g_A[n * FDIM + d] = v;
        g_S[n * FDIM + d] = v;
    }
}

// transpose W (64, NN) -> plane (1 or 2) of A and S.  Tile: 32 nodes x 64 dims.
__global__ void k_init_t(const float* __restrict__ Wimg, const float* __restrict__ Wtxt) {
    __shared__ float sm[64][33];
    const float* W = (blockIdx.y == 0) ? Wimg : Wtxt;
    int plane_off = (blockIdx.y == 0) ? 64 : 128;
    int n0 = blockIdx.x * 32;
    int tx = threadIdx.x;      // 0..31
    int ty = threadIdx.y;      // 0..7
    // load: coalesced over n
    #pragma unroll
    for (int k = 0; k < 8; k++) {
        int d = k * 8 + ty;
        sm[d][tx] = W[(size_t)d * NN + n0 + tx];
    }
    __syncthreads();
    // store: coalesced over d
    #pragma unroll
    for (int k = 0; k < 8; k++) {
        int row = k * 8 + ty;   // node within tile (0..63)? only 32 nodes per tile
        if (row < 32) {
            int n = n0 + row;
            #pragma unroll
            for (int dk = 0; dk < 2; dk++) {
                int d = dk * 32 + tx;
                float v = sm[d][row];
                g_A[n * FDIM + plane_off + d] = v;
                g_S[n * FDIM + plane_off + d] = v;
            }
        }
    }
}

// ---------------- fused SPMM + bias + sum-accumulate --------------------------
// warp per row; lane owns dims {2*lane, 2*lane+1} of each of the 3 planes
__global__ void k_spmm(const float* __restrict__ A, float* __restrict__ B,
                       const float* __restrict__ bias_i, const float* __restrict__ bias_t) {
    int warp = (blockIdx.x * blockDim.x + threadIdx.x) >> 5;
    int lane = threadIdx.x & 31;
    if (warp >= NN) return;
    int row = warp;
    int s = g_rowstart[row];
    int e = g_rowstart[row + 1];

    float a0 = 0.f, a1 = 0.f, i0 = 0.f, i1 = 0.f, t0 = 0.f, t1 = 0.f;
    int doff = lane * 2;
    for (int k = s; k < e; k++) {
        int   c = __ldg(&g_ecol[k]);
        float v = __ldg(&g_eval[k]);
        const float* xr = A + (size_t)c * FDIM;
        float2 xa = *(const float2*)(xr + doff);
        float2 xi = *(const float2*)(xr + 64 + doff);
        float2 xt = *(const float2*)(xr + 128 + doff);
        a0 += v * xa.x; a1 += v * xa.y;
        i0 += v * xi.x; i1 += v * xi.y;
        t0 += v * xt.x; t1 += v * xt.y;
    }
    // biases (applied to every row, matching reference spmm(x)+bias)
    float2 bi = *(const float2*)(bias_i + doff);
    float2 bt = *(const float2*)(bias_t + doff);
    i0 += bi.x; i1 += bi.y;
    t0 += bt.x; t1 += bt.y;

    float* br = B + (size_t)row * FDIM;
    float* sr = g_S + (size_t)row * FDIM;
    float2 w;
    w.x = a0; w.y = a1; *(float2*)(br + doff) = w;
    w.x = i0; w.y = i1; *(float2*)(br + 64 + doff) = w;
    w.x = t0; w.y = t1; *(float2*)(br + 128 + doff) = w;

    float2 sv;
    sv = *(float2*)(sr + doff);        sv.x += a0; sv.y += a1; *(float2*)(sr + doff) = sv;
    sv = *(float2*)(sr + 64 + doff);   sv.x += i0; sv.y += i1; *(float2*)(sr + 64 + doff) = sv;
    sv = *(float2*)(sr + 128 + doff);  sv.x += t0; sv.y += t1; *(float2*)(sr + 128 + doff) = sv;
}

// ---------------- final: mean, l2-normalize fusion, 9 gathers -----------------
// grid covers 3*BATCH rows (g = 0:user, 1:pos, 2:neg), warp per row
__global__ void k_final(const int* __restrict__ uidx, const int* __restrict__ pidx,
                        const int* __restrict__ nidx, float* __restrict__ out) {
    int warp = (blockIdx.x * blockDim.x + threadIdx.x) >> 5;
    int lane = threadIdx.x & 31;
    if (warp >= 3 * BATCH) return;
    int g = warp / BATCH;         // which index group
    int i = warp - g * BATCH;     // position within batch
    int idx = (g == 0) ? __ldg(&uidx[i]) : (g == 1) ? __ldg(&pidx[i]) : __ldg(&nidx[i]);
    int row = (g == 0) ? idx : (N_USERS + idx);

    const float* sr = g_S + (size_t)row * FDIM;
    int doff = lane * 2;
    const float inv = 0.25f;
    float2 me = *(const float2*)(sr + doff);        me.x *= inv; me.y *= inv;
    float2 mi = *(const float2*)(sr + 64 + doff);   mi.x *= inv; mi.y *= inv;
    float2 mt = *(const float2*)(sr + 128 + doff);  mt.x *= inv; mt.y *= inv;

    // warp-reduce squared norms of img and txt rows
    float sqi = mi.x * mi.x + mi.y * mi.y;
    float sqt = mt.x * mt.x + mt.y * mt.y;
    #pragma unroll
    for (int off = 16; off > 0; off >>= 1) {
        sqi += __shfl_xor_sync(0xFFFFFFFFu, sqi, off);
        sqt += __shfl_xor_sync(0xFFFFFFFFu, sqt, off);
    }
    float ni = fmaxf(sqrtf(sqi), 1e-12f);
    float nt = fmaxf(sqrtf(sqt), 1e-12f);
    float si = CAT_RATE / ni;
    float st = CAT_RATE / nt;

    float2 oe;
    oe.x = me.x + si * mi.x + st * mt.x;
    oe.y = me.y + si * mi.y + st * mt.y;

    size_t slot = (size_t)i * EMBED + doff;
    size_t grp  = (size_t)BATCH * EMBED;
    *(float2*)(out + (size_t)g * grp + slot)       = oe;   // groups 0-2: fused e
    *(float2*)(out + (size_t)(3 + g) * grp + slot) = mi;   // groups 3-5: mean img
    *(float2*)(out + (size_t)(6 + g) * grp + slot) = mt;   // groups 6-8: mean txt
}

// ---------------- launch ------------------------------------------------------
extern "C" void kernel_launch(void* const* d_in, const int* in_sizes, int n_in,
                              void* d_out, int out_size) {
    const int*   uidx   = (const int*)  d_in[0];
    const int*   pidx   = (const int*)  d_in[1];
    const int*   nidx   = (const int*)  d_in[2];
    const int*   arows  = (const int*)  d_in[3];
    const int*   acols  = (const int*)  d_in[4];
    const float* avals  = (const float*)d_in[5];
    const float* E0     = (const float*)d_in[6];
    const float* Wimg   = (const float*)d_in[7];
    const float* Bimg   = (const float*)d_in[8];
    const float* Wtxt   = (const float*)d_in[9];
    const float* Btxt   = (const float*)d_in[10];
    float* out = (float*)d_out;

    // raw pointers to __device__ globals for spmm args (ping-pong)
    float *A, *B, *S;
    cudaGetSymbolAddress((void**)&A, g_A);
    cudaGetSymbolAddress((void**)&B, g_B);
    cudaGetSymbolAddress((void**)&S, g_S);

    // CSR build
    k_zero_counts<<<(NN + 255) / 256, 256>>>();
    k_hist<<<(NEDGES + 255) / 256, 256>>>(arows);
    k_scan_p1<<<SCAN_NB, SCAN_T>>>();
    k_scan_p2<<<1, 32>>>();
    k_scan_p3<<<SCAN_NB, SCAN_T>>>();
    k_scatter<<<(NEDGES + 255) / 256, 256>>>(arows, acols, avals);

    // feature init: A = S = [E0 | Wimg^T | Wtxt^T]
    k_init_e<<<(NN * EMBED + 255) / 256, 256>>>(E0);
    {
        dim3 gb(NN / 32, 2);
        dim3 tb(32, 8);
        k_init_t<<<gb, tb>>>(Wimg, Wtxt);
    }

    // 3 propagation layers (fused spmm + bias + S accumulate), ping-pong A/B
    int spmm_blocks = (NN * 32 + 255) / 256;
    k_spmm<<<spmm_blocks, 256>>>(A, B, Bimg, Btxt);
    k_spmm<<<spmm_blocks, 256>>>(B, A, Bimg, Btxt);
    k_spmm<<<spmm_blocks, 256>>>(A, B, Bimg, Btxt);

    // final fused mean / normalize / gather
    int fin_blocks = (3 * BATCH * 32 + 255) / 256;
    k_final<<<fin_blocks, 256>>>(uidx, pidx, nidx, out);
}

// round 2
// speedup vs baseline: 1.8500x; 1.8500x over previous
#include <cuda_runtime.h>
#include <cuda_fp16.h>

#define N_USERS 50000
#define NN      100000        // total nodes
#define EMBED   64
#define FDIM    192           // 3 streams interleaved: [e | img | txt]
#define NEDGES  1600000
#define BATCH   4096
#define CAT_RATE 0.02f

// ---------------- device scratch ----------------------------------------------
// 4 layer buffers in fp16 (layer 0 = inputs, layers 1..3 = propagation outputs)
__device__ __half g_F0[NN * FDIM];
__device__ __half g_F1[NN * FDIM];
__device__ __half g_F2[NN * FDIM];
__device__ __half g_F3[NN * FDIM];
__device__ int   g_count[NN];
__device__ int   g_rowstart[NN + 1];
__device__ int   g_cursor[NN];
__device__ int2  g_edge[NEDGES];     // (col, val-as-int-bits)
__device__ int   g_blocksums[256];

// ---------------- CSR build ---------------------------------------------------
__global__ void k_zero_counts() {
    int i = blockIdx.x * blockDim.x + threadIdx.x;
    if (i < NN) g_count[i] = 0;
}

__global__ void k_hist(const int* __restrict__ rows) {
    int e = blockIdx.x * blockDim.x + threadIdx.x;
    if (e < NEDGES) atomicAdd(&g_count[rows[e]], 1);
}

#define SCAN_T 512
#define SCAN_NB ((NN + SCAN_T - 1) / SCAN_T)   // 196

__global__ void k_scan_p1() {   // per-block sums
    __shared__ int sm[SCAN_T];
    int i = blockIdx.x * SCAN_T + threadIdx.x;
    sm[threadIdx.x] = (i < NN) ? g_count[i] : 0;
    __syncthreads();
    for (int off = SCAN_T / 2; off > 0; off >>= 1) {
        if (threadIdx.x < off) sm[threadIdx.x] += sm[threadIdx.x + off];
        __syncthreads();
    }
    if (threadIdx.x == 0) g_blocksums[blockIdx.x] = sm[0];
}

__global__ void k_scan_p2() {   // parallel exclusive scan of 196 block sums
    __shared__ int sm[256];
    int t = threadIdx.x;
    int v = (t < SCAN_NB) ? g_blocksums[t] : 0;
    sm[t] = v;
    __syncthreads();
    for (int off = 1; off < 256; off <<= 1) {
        int a = (t >= off) ? sm[t - off] : 0;
        __syncthreads();
        sm[t] += a;
        __syncthreads();
    }
    if (t < SCAN_NB) g_blocksums[t] = sm[t] - v;   // exclusive
}

__global__ void k_scan_p3() {   // exclusive scan within block + offset
    __shared__ int sm[SCAN_T];
    int i = blockIdx.x * SCAN_T + threadIdx.x;
    int v = (i < NN) ? g_count[i] : 0;
    sm[threadIdx.x] = v;
    __syncthreads();
    for (int off = 1; off < SCAN_T; off <<= 1) {
        int add = (threadIdx.x >= off) ? sm[threadIdx.x - off] : 0;
        __syncthreads();
        sm[threadIdx.x] += add;
        __syncthreads();
    }
    int excl = sm[threadIdx.x] - v + g_blocksums[blockIdx.x];
    if (i < NN) {
        g_rowstart[i] = excl;
        g_cursor[i]   = excl;
    }
    if (i == 0) g_rowstart[NN] = NEDGES;
}

__global__ void k_scatter(const int* __restrict__ rows, const int* __restrict__ cols,
                          const float* __restrict__ vals) {
    int e = blockIdx.x * blockDim.x + threadIdx.x;
    if (e < NEDGES) {
        int r = rows[e];
        int p = atomicAdd(&g_cursor[r], 1);
        g_edge[p] = make_int2(cols[e], __float_as_int(vals[e]));
    }
}

// ---------------- feature init ------------------------------------------------
// E0 (N,64) fp32 -> plane 0 of F0 (fp16)
__global__ void k_init_e(const float* __restrict__ E0) {
    int i = blockIdx.x * blockDim.x + threadIdx.x;   // over NN*64
    if (i < NN * EMBED) {
        int n = i >> 6, d = i & 63;
        g_F0[n * FDIM + d] = __float2half_rn(E0[i]);
    }
}

// transpose W (64, NN) -> plane (1 or 2) of F0 (fp16). Tile: 32 nodes x 64 dims.
__global__ void k_init_t(const float* __restrict__ Wimg, const float* __restrict__ Wtxt) {
    __shared__ float sm[64][33];
    const float* W = (blockIdx.y == 0) ? Wimg : Wtxt;
    int plane_off = (blockIdx.y == 0) ? 64 : 128;
    int n0 = blockIdx.x * 32;
    int tx = threadIdx.x;      // 0..31
    int ty = threadIdx.y;      // 0..7
    #pragma unroll
    for (int k = 0; k < 8; k++) {
        int d = k * 8 + ty;
        sm[d][tx] = W[(size_t)d * NN + n0 + tx];
    }
    __syncthreads();
    #pragma unroll
    for (int k = 0; k < 8; k++) {
        int row = k * 8 + ty;
        if (row < 32) {
            int n = n0 + row;
            #pragma unroll
            for (int dk = 0; dk < 2; dk++) {
                int d = dk * 32 + tx;
                g_F0[n * FDIM + plane_off + d] = __float2half_rn(sm[d][row]);
            }
        }
    }
}

// ---------------- fused SPMM + bias (fp16 in/out, fp32 accum) -----------------
// warp per row; lane owns dims {2*lane, 2*lane+1} of each of the 3 planes
__global__ void k_spmm(const __half* __restrict__ A, __half* __restrict__ B,
                       const float* __restrict__ bias_i, const float* __restrict__ bias_t) {
    int warp = (blockIdx.x * blockDim.x + threadIdx.x) >> 5;
    int lane = threadIdx.x & 31;
    if (warp >= NN) return;
    int s = g_rowstart[warp];
    int e = g_rowstart[warp + 1];

    float a0 = 0.f, a1 = 0.f, i0 = 0.f, i1 = 0.f, t0 = 0.f, t1 = 0.f;
    for (int k = s; k < e; k++) {
        int2  ed = __ldg(&g_edge[k]);
        float v  = __int_as_float(ed.y);
        const __half2* xr = (const __half2*)(A + (size_t)ed.x * FDIM);
        float2 f0 = __half22float2(xr[lane]);
        float2 f1 = __half22float2(xr[32 + lane]);
        float2 f2 = __half22float2(xr[64 + lane]);
        a0 += v * f0.x; a1 += v * f0.y;
        i0 += v * f1.x; i1 += v * f1.y;
        t0 += v * f2.x; t1 += v * f2.y;
    }
    int doff = lane * 2;
    float2 bi = *(const float2*)(bias_i + doff);
    float2 bt = *(const float2*)(bias_t + doff);

    __half2* br = (__half2*)(B + (size_t)warp * FDIM);
    br[lane]      = __floats2half2_rn(a0, a1);
    br[32 + lane] = __floats2half2_rn(i0 + bi.x, i1 + bi.y);
    br[64 + lane] = __floats2half2_rn(t0 + bt.x, t1 + bt.y);
}

// ---------------- final: sum 4 layers, mean, l2-normalize fusion, gathers -----
__global__ void k_final(const int* __restrict__ uidx, const int* __restrict__ pidx,
                        const int* __restrict__ nidx, float* __restrict__ out) {
    int warp = (blockIdx.x * blockDim.x + threadIdx.x) >> 5;
    int lane = threadIdx.x & 31;
    if (warp >= 3 * BATCH) return;
    int g = warp / BATCH;
    int i = warp - g * BATCH;
    int idx = (g == 0) ? __ldg(&uidx[i]) : (g == 1) ? __ldg(&pidx[i]) : __ldg(&nidx[i]);
    int row = (g == 0) ? idx : (N_USERS + idx);

    size_t base = (size_t)row * FDIM;
    const __half2* r0 = (const __half2*)(g_F0 + base);
    const __half2* r1 = (const __half2*)(g_F1 + base);
    const __half2* r2 = (const __half2*)(g_F2 + base);
    const __half2* r3 = (const __half2*)(g_F3 + base);

    const float inv = 0.25f;
    float2 me, mi, mt;
    {
        float2 a = __half22float2(r0[lane]),      b = __half22float2(r1[lane]);
        float2 c = __half22float2(r2[lane]),      d = __half22float2(r3[lane]);
        me.x = (a.x + b.x + c.x + d.x) * inv;  me.y = (a.y + b.y + c.y + d.y) * inv;
    }
    {
        float2 a = __half22float2(r0[32 + lane]), b = __half22float2(r1[32 + lane]);
        float2 c = __half22float2(r2[32 + lane]), d = __half22float2(r3[32 + lane]);
        mi.x = (a.x + b.x + c.x + d.x) * inv;  mi.y = (a.y + b.y + c.y + d.y) * inv;
    }
    {
        float2 a = __half22float2(r0[64 + lane]), b = __half22float2(r1[64 + lane]);
        float2 c = __half22float2(r2[64 + lane]), d = __half22float2(r3[64 + lane]);
        mt.x = (a.x + b.x + c.x + d.x) * inv;  mt.y = (a.y + b.y + c.y + d.y) * inv;
    }

    float sqi = mi.x * mi.x + mi.y * mi.y;
    float sqt = mt.x * mt.x + mt.y * mt.y;
    #pragma unroll
    for (int off = 16; off > 0; off >>= 1) {
        sqi += __shfl_xor_sync(0xFFFFFFFFu, sqi, off);
        sqt += __shfl_xor_sync(0xFFFFFFFFu, sqt, off);
    }
    float si = CAT_RATE / fmaxf(sqrtf(sqi), 1e-12f);
    float st = CAT_RATE / fmaxf(sqrtf(sqt), 1e-12f);

    float2 oe;
    oe.x = me.x + si * mi.x + st * mt.x;
    oe.y = me.y + si * mi.y + st * mt.y;

    int doff = lane * 2;
    size_t slot = (size_t)i * EMBED + doff;
    size_t grp  = (size_t)BATCH * EMBED;
    *(float2*)(out + (size_t)g * grp + slot)       = oe;
    *(float2*)(out + (size_t)(3 + g) * grp + slot) = mi;
    *(float2*)(out + (size_t)(6 + g) * grp + slot) = mt;
}

// ---------------- launch ------------------------------------------------------
extern "C" void kernel_launch(void* const* d_in, const int* in_sizes, int n_in,
                              void* d_out, int out_size) {
    const int*   uidx   = (const int*)  d_in[0];
    const int*   pidx   = (const int*)  d_in[1];
    const int*   nidx   = (const int*)  d_in[2];
    const int*   arows  = (const int*)  d_in[3];
    const int*   acols  = (const int*)  d_in[4];
    const float* avals  = (const float*)d_in[5];
    const float* E0     = (const float*)d_in[6];
    const float* Wimg   = (const float*)d_in[7];
    const float* Bimg   = (const float*)d_in[8];
    const float* Wtxt   = (const float*)d_in[9];
    const float* Btxt   = (const float*)d_in[10];
    float* out = (float*)d_out;

    __half *F0, *F1, *F2, *F3;
    cudaGetSymbolAddress((void**)&F0, g_F0);
    cudaGetSymbolAddress((void**)&F1, g_F1);
    cudaGetSymbolAddress((void**)&F2, g_F2);
    cudaGetSymbolAddress((void**)&F3, g_F3);

    // CSR build
    k_zero_counts<<<(NN + 255) / 256, 256>>>();
    k_hist<<<(NEDGES + 255) / 256, 256>>>(arows);
    k_scan_p1<<<SCAN_NB, SCAN_T>>>();
    k_scan_p2<<<1, 256>>>();
    k_scan_p3<<<SCAN_NB, SCAN_T>>>();
    k_scatter<<<(NEDGES + 255) / 256, 256>>>(arows, acols, avals);

    // feature init: F0 = [E0 | Wimg^T | Wtxt^T] in fp16
    k_init_e<<<(NN * EMBED + 255) / 256, 256>>>(E0);
    {
        dim3 gb(NN / 32, 2);
        dim3 tb(32, 8);
        k_init_t<<<gb, tb>>>(Wimg, Wtxt);
    }

    // 3 propagation layers
    int spmm_blocks = (NN * 32 + 255) / 256;
    k_spmm<<<spmm_blocks, 256>>>(F0, F1, Bimg, Btxt);
    k_spmm<<<spmm_blocks, 256>>>(F1, F2, Bimg, Btxt);
    k_spmm<<<spmm_blocks, 256>>>(F2, F3, Bimg, Btxt);

    // final fused sum / mean / normalize / gather
    int fin_blocks = (3 * BATCH * 32 + 255) / 256;
    k_final<<<fin_blocks, 256>>>(uidx, pidx, nidx, out);
}

// round 3
// speedup vs baseline: 2.0014x; 1.0818x over previous
#include <cuda_runtime.h>
#include <cuda_fp16.h>

#define N_USERS 50000
#define NN      100000        // total nodes
#define EMBED   64
#define FDIM    192           // 3 streams interleaved: [e | img | txt]
#define NEDGES  1600000
#define BATCH   4096
#define CAT_RATE 0.02f

// ---------------- device scratch ----------------------------------------------
__device__ __half g_F0[NN * FDIM];
__device__ __half g_F1[NN * FDIM];
__device__ __half g_F2[NN * FDIM];
__device__ __half g_F3[NN * FDIM];
__device__ int   g_count[NN];        // zero at load; re-zeroed at end of each launch
__device__ int   g_rowstart[NN + 1];
__device__ int   g_cursor[NN];
__device__ int2  g_edge[NEDGES];     // (col, val-as-int-bits)
__device__ int   g_blocksums[256];

// ---------------- fused: hist + init_e + init_t -------------------------------
// block ranges:  [0, NB_HIST)           -> edge histogram
//                [NB_HIST, +NB_INITE)   -> E0 copy (float4 vectorized)
//                [.., +2*NB_TILES)      -> W transpose (img, txt)
#define NB_HIST  ((NEDGES + 255) / 256)          // 6250
#define NB_INITE ((NN * EMBED / 4 + 255) / 256)  // 6250
#define NB_TILES (NN / 32)                       // 3125
#define NB_FUSED (NB_HIST + NB_INITE + 2 * NB_TILES)

__global__ void k_fused_hist_init(const int* __restrict__ rows,
                                  const float* __restrict__ E0,
                                  const float* __restrict__ Wimg,
                                  const float* __restrict__ Wtxt) {
    __shared__ float sm[64][33];
    int b = blockIdx.x;
    if (b < NB_HIST) {
        int e = b * 256 + threadIdx.x;
        if (e < NEDGES) atomicAdd(&g_count[rows[e]], 1);
        return;
    }
    b -= NB_HIST;
    if (b < NB_INITE) {
        int i = b * 256 + threadIdx.x;           // over NN*16 float4s
        if (i < NN * (EMBED / 4)) {
            int n  = i >> 4;
            int d4 = (i & 15) * 4;
            float4 v = ((const float4*)E0)[i];
            __half2* dst = (__half2*)(g_F0 + (size_t)n * FDIM + d4);
            dst[0] = __floats2half2_rn(v.x, v.y);
            dst[1] = __floats2half2_rn(v.z, v.w);
        }
        return;
    }
    b -= NB_INITE;
    const float* W = (b < NB_TILES) ? Wimg : Wtxt;
    int plane_off  = (b < NB_TILES) ? 64 : 128;
    int tile = (b < NB_TILES) ? b : (b - NB_TILES);
    int n0 = tile * 32;
    int tx = threadIdx.x & 31;
    int ty = threadIdx.x >> 5;   // 0..7
    #pragma unroll
    for (int k = 0; k < 8; k++) {
        int d = k * 8 + ty;
        sm[d][tx] = W[(size_t)d * NN + n0 + tx];
    }
    __syncthreads();
    #pragma unroll
    for (int k = 0; k < 4; k++) {
        int row = k * 8 + ty;    // 0..31 nodes in tile
        int n = n0 + row;
        #pragma unroll
        for (int dk = 0; dk < 2; dk++) {
            int d = dk * 32 + tx;
            g_F0[(size_t)n * FDIM + plane_off + d] = __float2half_rn(sm[d][row]);
        }
    }
}

// ---------------- scan --------------------------------------------------------
#define SCAN_T 512
#define SCAN_NB ((NN + SCAN_T - 1) / SCAN_T)   // 196

__global__ void k_scan_p1() {   // raw per-block sums
    __shared__ int sm[SCAN_T];
    int i = blockIdx.x * SCAN_T + threadIdx.x;
    sm[threadIdx.x] = (i < NN) ? g_count[i] : 0;
    __syncthreads();
    for (int off = SCAN_T / 2; off > 0; off >>= 1) {
        if (threadIdx.x < off) sm[threadIdx.x] += sm[threadIdx.x + off];
        __syncthreads();
    }
    if (threadIdx.x == 0) g_blocksums[blockIdx.x] = sm[0];
}

__global__ void k_scan_p3() {   // per-block: reduce prefix of blocksums, then local scan
    __shared__ int sm[SCAN_T];
    __shared__ int s_off;
    // 1) block offset = sum of blocksums[0..blockIdx.x)
    int contrib = (threadIdx.x < blockIdx.x) ? g_blocksums[threadIdx.x] : 0;
    sm[threadIdx.x] = contrib;
    __syncthreads();
    for (int off = SCAN_T / 2; off > 0; off >>= 1) {
        if (threadIdx.x < off) sm[threadIdx.x] += sm[threadIdx.x + off];
        __syncthreads();
    }
    if (threadIdx.x == 0) s_off = sm[0];
    __syncthreads();
    // 2) local Hillis-Steele inclusive scan
    int i = blockIdx.x * SCAN_T + threadIdx.x;
    int v = (i < NN) ? g_count[i] : 0;
    sm[threadIdx.x] = v;
    __syncthreads();
    for (int off = 1; off < SCAN_T; off <<= 1) {
        int add = (threadIdx.x >= off) ? sm[threadIdx.x - off] : 0;
        __syncthreads();
        sm[threadIdx.x] += add;
        __syncthreads();
    }
    int excl = sm[threadIdx.x] - v + s_off;
    if (i < NN) {
        g_rowstart[i] = excl;
        g_cursor[i]   = excl;
    }
    if (i == 0) g_rowstart[NN] = NEDGES;
}

__global__ void k_scatter(const int* __restrict__ rows, const int* __restrict__ cols,
                          const float* __restrict__ vals) {
    int e = blockIdx.x * blockDim.x + threadIdx.x;
    if (e < NEDGES) {
        int r = rows[e];
        int p = atomicAdd(&g_cursor[r], 1);
        g_edge[p] = make_int2(cols[e], __float_as_int(vals[e]));
    }
}

// ---------------- fused SPMM + bias (fp16 in/out, fp32 accum) -----------------
__global__ void k_spmm(const __half* __restrict__ A, __half* __restrict__ B,
                       const float* __restrict__ bias_i, const float* __restrict__ bias_t) {
    int warp = (blockIdx.x * blockDim.x + threadIdx.x) >> 5;
    int lane = threadIdx.x & 31;
    if (warp >= NN) return;
    int s = g_rowstart[warp];
    int e = g_rowstart[warp + 1];

    float a0 = 0.f, a1 = 0.f, i0 = 0.f, i1 = 0.f, t0 = 0.f, t1 = 0.f;
    int k = s;
    for (; k + 1 < e; k += 2) {
        int2  eA = __ldg(&g_edge[k]);
        int2  eB = __ldg(&g_edge[k + 1]);
        float vA = __int_as_float(eA.y);
        float vB = __int_as_float(eB.y);
        const __half2* xA = (const __half2*)(A + (size_t)eA.x * FDIM);
        const __half2* xB = (const __half2*)(A + (size_t)eB.x * FDIM);
        float2 fA0 = __half22float2(xA[lane]);
        float2 fA1 = __half22float2(xA[32 + lane]);
        float2 fA2 = __half22float2(xA[64 + lane]);
        float2 fB0 = __half22float2(xB[lane]);
        float2 fB1 = __half22float2(xB[32 + lane]);
        float2 fB2 = __half22float2(xB[64 + lane]);
        a0 += vA * fA0.x; a1 += vA * fA0.y;
        i0 += vA * fA1.x; i1 += vA * fA1.y;
        t0 += vA * fA2.x; t1 += vA * fA2.y;
        a0 += vB * fB0.x; a1 += vB * fB0.y;
        i0 += vB * fB1.x; i1 += vB * fB1.y;
        t0 += vB * fB2.x; t1 += vB * fB2.y;
    }
    if (k < e) {
        int2  ed = __ldg(&g_edge[k]);
        float v  = __int_as_float(ed.y);
        const __half2* xr = (const __half2*)(A + (size_t)ed.x * FDIM);
        float2 f0 = __half22float2(xr[lane]);
        float2 f1 = __half22float2(xr[32 + lane]);
        float2 f2 = __half22float2(xr[64 + lane]);
        a0 += v * f0.x; a1 += v * f0.y;
        i0 += v * f1.x; i1 += v * f1.y;
        t0 += v * f2.x; t1 += v * f2.y;
    }
    int doff = lane * 2;
    float2 bi = *(const float2*)(bias_i + doff);
    float2 bt = *(const float2*)(bias_t + doff);

    __half2* br = (__half2*)(B + (size_t)warp * FDIM);
    br[lane]      = __floats2half2_rn(a0, a1);
    br[32 + lane] = __floats2half2_rn(i0 + bi.x, i1 + bi.y);
    br[64 + lane] = __floats2half2_rn(t0 + bt.x, t1 + bt.y);
}

// ---------------- final: sum 4 layers, mean, l2 fusion, gathers, + count reset
#define FIN_BLOCKS ((3 * BATCH * 32 + 255) / 256)          // 1536
#define ZERO_BLOCKS ((NN + 255) / 256)                     // 391

__global__ void k_final(const int* __restrict__ uidx, const int* __restrict__ pidx,
                        const int* __restrict__ nidx, float* __restrict__ out) {
    if (blockIdx.x >= FIN_BLOCKS) {
        // reset g_count for the next launch (globals start zeroed at load)
        int i = (blockIdx.x - FIN_BLOCKS) * 256 + threadIdx.x;
        if (i < NN) g_count[i] = 0;
        return;
    }
    int warp = (blockIdx.x * blockDim.x + threadIdx.x) >> 5;
    int lane = threadIdx.x & 31;
    int g = warp / BATCH;
    int i = warp - g * BATCH;
    int idx = (g == 0) ? __ldg(&uidx[i]) : (g == 1) ? __ldg(&pidx[i]) : __ldg(&nidx[i]);
    int row = (g == 0) ? idx : (N_USERS + idx);

    size_t base = (size_t)row * FDIM;
    const __half2* r0 = (const __half2*)(g_F0 + base);
    const __half2* r1 = (const __half2*)(g_F1 + base);
    const __half2* r2 = (const __half2*)(g_F2 + base);
    const __half2* r3 = (const __half2*)(g_F3 + base);

    const float inv = 0.25f;
    float2 me, mi, mt;
    {
        float2 a = __half22float2(r0[lane]),      b = __half22float2(r1[lane]);
        float2 c = __half22float2(r2[lane]),      d = __half22float2(r3[lane]);
        me.x = (a.x + b.x + c.x + d.x) * inv;  me.y = (a.y + b.y + c.y + d.y) * inv;
    }
    {
        float2 a = __half22float2(r0[32 + lane]), b = __half22float2(r1[32 + lane]);
        float2 c = __half22float2(r2[32 + lane]), d = __half22float2(r3[32 + lane]);
        mi.x = (a.x + b.x + c.x + d.x) * inv;  mi.y = (a.y + b.y + c.y + d.y) * inv;
    }
    {
        float2 a = __half22float2(r0[64 + lane]), b = __half22float2(r1[64 + lane]);
        float2 c = __half22float2(r2[64 + lane]), d = __half22float2(r3[64 + lane]);
        mt.x = (a.x + b.x + c.x + d.x) * inv;  mt.y = (a.y + b.y + c.y + d.y) * inv;
    }

    float sqi = mi.x * mi.x + mi.y * mi.y;
    float sqt = mt.x * mt.x + mt.y * mt.y;
    #pragma unroll
    for (int off = 16; off > 0; off >>= 1) {
        sqi += __shfl_xor_sync(0xFFFFFFFFu, sqi, off);
        sqt += __shfl_xor_sync(0xFFFFFFFFu, sqt, off);
    }
    float si = CAT_RATE / fmaxf(sqrtf(sqi), 1e-12f);
    float st = CAT_RATE / fmaxf(sqrtf(sqt), 1e-12f);

    float2 oe;
    oe.x = me.x + si * mi.x + st * mt.x;
    oe.y = me.y + si * mi.y + st * mt.y;

    int doff = lane * 2;
    size_t slot = (size_t)i * EMBED + doff;
    size_t grp  = (size_t)BATCH * EMBED;
    *(float2*)(out + (size_t)g * grp + slot)       = oe;
    *(float2*)(out + (size_t)(3 + g) * grp + slot) = mi;
    *(float2*)(out + (size_t)(6 + g) * grp + slot) = mt;
}

// ---------------- launch ------------------------------------------------------
extern "C" void kernel_launch(void* const* d_in, const int* in_sizes, int n_in,
                              void* d_out, int out_size) {
    const int*   uidx   = (const int*)  d_in[0];
    const int*   pidx   = (const int*)  d_in[1];
    const int*   nidx   = (const int*)  d_in[2];
    const int*   arows  = (const int*)  d_in[3];
    const int*   acols  = (const int*)  d_in[4];
    const float* avals  = (const float*)d_in[5];
    const float* E0     = (const float*)d_in[6];
    const float* Wimg   = (const float*)d_in[7];
    const float* Bimg   = (const float*)d_in[8];
    const float* Wtxt   = (const float*)d_in[9];
    const float* Btxt   = (const float*)d_in[10];
    float* out = (float*)d_out;

    __half *F0, *F1, *F2, *F3;
    cudaGetSymbolAddress((void**)&F0, g_F0);
    cudaGetSymbolAddress((void**)&F1, g_F1);
    cudaGetSymbolAddress((void**)&F2, g_F2);
    cudaGetSymbolAddress((void**)&F3, g_F3);

    // fused histogram + feature init (independent work, one grid)
    k_fused_hist_init<<<NB_FUSED, 256>>>(arows, E0, Wimg, Wtxt);

    // CSR offsets
    k_scan_p1<<<SCAN_NB, SCAN_T>>>();
    k_scan_p3<<<SCAN_NB, SCAN_T>>>();
    k_scatter<<<(NEDGES + 255) / 256, 256>>>(arows, acols, avals);

    // 3 propagation layers
    int spmm_blocks = (NN * 32 + 255) / 256;
    k_spmm<<<spmm_blocks, 256>>>(F0, F1, Bimg, Btxt);
    k_spmm<<<spmm_blocks, 256>>>(F1, F2, Bimg, Btxt);
    k_spmm<<<spmm_blocks, 256>>>(F2, F3, Bimg, Btxt);

    // final fused sum / mean / normalize / gather  (+ g_count reset for next call)
    k_final<<<FIN_BLOCKS + ZERO_BLOCKS, 256>>>(uidx, pidx, nidx, out);
}

// round 4
// speedup vs baseline: 2.4420x; 1.2202x over previous
#include <cuda_runtime.h>
#include <cuda_fp16.h>

#define N_USERS 50000
#define NN      100000        // total nodes
#define EMBED   64
#define FDIM    192           // 3 streams interleaved: [e | img | txt]
#define NEDGES  1600000
#define BATCH   4096
#define CAT_RATE 0.02f

// ---------------- device scratch ----------------------------------------------
__device__ __half g_F0[NN * FDIM];
__device__ __half g_F1[NN * FDIM];
__device__ __half g_F2[NN * FDIM];
__device__ int   g_count[NN];        // zero at load; re-zeroed at end of each launch
__device__ int   g_rowstart[NN + 1];
__device__ int   g_cursor[NN];
__device__ int2  g_edge[NEDGES];     // (col, val-as-int-bits)
__device__ int   g_blocksums[256];

// ---------------- fused: hist + init_e + init_t -------------------------------
#define NB_HIST  ((NEDGES + 255) / 256)          // 6250
#define NB_INITE ((NN * EMBED / 4 + 255) / 256)  // 6250
#define NB_TILES (NN / 32)                       // 3125
#define NB_FUSED (NB_HIST + NB_INITE + 2 * NB_TILES)

__global__ void k_fused_hist_init(const int* __restrict__ rows,
                                  const float* __restrict__ E0,
                                  const float* __restrict__ Wimg,
                                  const float* __restrict__ Wtxt) {
    __shared__ float sm[64][33];
    int b = blockIdx.x;
    if (b < NB_HIST) {
        int e = b * 256 + threadIdx.x;
        if (e < NEDGES) atomicAdd(&g_count[rows[e]], 1);
        return;
    }
    b -= NB_HIST;
    if (b < NB_INITE) {
        int i = b * 256 + threadIdx.x;           // over NN*16 float4s
        if (i < NN * (EMBED / 4)) {
            int n  = i >> 4;
            int d4 = (i & 15) * 4;
            float4 v = ((const float4*)E0)[i];
            __half2* dst = (__half2*)(g_F0 + (size_t)n * FDIM + d4);
            dst[0] = __floats2half2_rn(v.x, v.y);
            dst[1] = __floats2half2_rn(v.z, v.w);
        }
        return;
    }
    b -= NB_INITE;
    const float* W = (b < NB_TILES) ? Wimg : Wtxt;
    int plane_off  = (b < NB_TILES) ? 64 : 128;
    int tile = (b < NB_TILES) ? b : (b - NB_TILES);
    int n0 = tile * 32;
    int tx = threadIdx.x & 31;
    int ty = threadIdx.x >> 5;   // 0..7
    #pragma unroll
    for (int k = 0; k < 8; k++) {
        int d = k * 8 + ty;
        sm[d][tx] = W[(size_t)d * NN + n0 + tx];
    }
    __syncthreads();
    #pragma unroll
    for (int k = 0; k < 4; k++) {
        int row = k * 8 + ty;    // 0..31 nodes in tile
        int n = n0 + row;
        #pragma unroll
        for (int dk = 0; dk < 2; dk++) {
            int d = dk * 32 + tx;
            g_F0[(size_t)n * FDIM + plane_off + d] = __float2half_rn(sm[d][row]);
        }
    }
}

// ---------------- scan --------------------------------------------------------
#define SCAN_T 512
#define SCAN_NB ((NN + SCAN_T - 1) / SCAN_T)   // 196

__global__ void k_scan_p1() {   // raw per-block sums
    __shared__ int sm[SCAN_T];
    int i = blockIdx.x * SCAN_T + threadIdx.x;
    sm[threadIdx.x] = (i < NN) ? g_count[i] : 0;
    __syncthreads();
    for (int off = SCAN_T / 2; off > 0; off >>= 1) {
        if (threadIdx.x < off) sm[threadIdx.x] += sm[threadIdx.x + off];
        __syncthreads();
    }
    if (threadIdx.x == 0) g_blocksums[blockIdx.x] = sm[0];
}

__global__ void k_scan_p3() {   // per-block: prefix of blocksums + local scan
    __shared__ int sm[SCAN_T];
    __shared__ int s_off;
    int contrib = (threadIdx.x < blockIdx.x) ? g_blocksums[threadIdx.x] : 0;
    sm[threadIdx.x] = contrib;
    __syncthreads();
    for (int off = SCAN_T / 2; off > 0; off >>= 1) {
        if (threadIdx.x < off) sm[threadIdx.x] += sm[threadIdx.x + off];
        __syncthreads();
    }
    if (threadIdx.x == 0) s_off = sm[0];
    __syncthreads();
    int i = blockIdx.x * SCAN_T + threadIdx.x;
    int v = (i < NN) ? g_count[i] : 0;
    sm[threadIdx.x] = v;
    __syncthreads();
    for (int off = 1; off < SCAN_T; off <<= 1) {
        int add = (threadIdx.x >= off) ? sm[threadIdx.x - off] : 0;
        __syncthreads();
        sm[threadIdx.x] += add;
        __syncthreads();
    }
    int excl = sm[threadIdx.x] - v + s_off;
    if (i < NN) {
        g_rowstart[i] = excl;
        g_cursor[i]   = excl;
    }
    if (i == 0) g_rowstart[NN] = NEDGES;
}

__global__ void k_scatter(const int* __restrict__ rows, const int* __restrict__ cols,
                          const float* __restrict__ vals) {
    int e = blockIdx.x * blockDim.x + threadIdx.x;
    if (e < NEDGES) {
        int r = rows[e];
        int p = atomicAdd(&g_cursor[r], 1);
        g_edge[p] = make_int2(cols[e], __float_as_int(vals[e]));
    }
}

// ---------------- fused SPMM + bias (fp16 in/out, fp32 accum) -----------------
__global__ void k_spmm(const __half* __restrict__ A, __half* __restrict__ B,
                       const float* __restrict__ bias_i, const float* __restrict__ bias_t) {
    int warp = (blockIdx.x * blockDim.x + threadIdx.x) >> 5;
    int lane = threadIdx.x & 31;
    if (warp >= NN) return;
    int s = g_rowstart[warp];
    int e = g_rowstart[warp + 1];

    float a0 = 0.f, a1 = 0.f, i0 = 0.f, i1 = 0.f, t0 = 0.f, t1 = 0.f;
    int k = s;
    for (; k + 1 < e; k += 2) {
        int2  eA = __ldg(&g_edge[k]);
        int2  eB = __ldg(&g_edge[k + 1]);
        float vA = __int_as_float(eA.y);
        float vB = __int_as_float(eB.y);
        const __half2* xA = (const __half2*)(A + (size_t)eA.x * FDIM);
        const __half2* xB = (const __half2*)(A + (size_t)eB.x * FDIM);
        float2 fA0 = __half22float2(xA[lane]);
        float2 fA1 = __half22float2(xA[32 + lane]);
        float2 fA2 = __half22float2(xA[64 + lane]);
        float2 fB0 = __half22float2(xB[lane]);
        float2 fB1 = __half22float2(xB[32 + lane]);
        float2 fB2 = __half22float2(xB[64 + lane]);
        a0 += vA * fA0.x; a1 += vA * fA0.y;
        i0 += vA * fA1.x; i1 += vA * fA1.y;
        t0 += vA * fA2.x; t1 += vA * fA2.y;
        a0 += vB * fB0.x; a1 += vB * fB0.y;
        i0 += vB * fB1.x; i1 += vB * fB1.y;
        t0 += vB * fB2.x; t1 += vB * fB2.y;
    }
    if (k < e) {
        int2  ed = __ldg(&g_edge[k]);
        float v  = __int_as_float(ed.y);
        const __half2* xr = (const __half2*)(A + (size_t)ed.x * FDIM);
        float2 f0 = __half22float2(xr[lane]);
        float2 f1 = __half22float2(xr[32 + lane]);
        float2 f2 = __half22float2(xr[64 + lane]);
        a0 += v * f0.x; a1 += v * f0.y;
        i0 += v * f1.x; i1 += v * f1.y;
        t0 += v * f2.x; t1 += v * f2.y;
    }
    int doff = lane * 2;
    float2 bi = *(const float2*)(bias_i + doff);
    float2 bt = *(const float2*)(bias_t + doff);

    __half2* br = (__half2*)(B + (size_t)warp * FDIM);
    br[lane]      = __floats2half2_rn(a0, a1);
    br[32 + lane] = __floats2half2_rn(i0 + bi.x, i1 + bi.y);
    br[64 + lane] = __floats2half2_rn(t0 + bt.x, t1 + bt.y);
}

// ---------------- final: on-the-fly layer-3 + sum + mean + l2 + gathers -------
// warp per output slot; also resets g_count in trailing blocks
#define FIN_BLOCKS ((3 * BATCH * 32 + 255) / 256)          // 1536
#define ZERO_BLOCKS ((NN + 255) / 256)                     // 391

__global__ void k_final(const int* __restrict__ uidx, const int* __restrict__ pidx,
                        const int* __restrict__ nidx,
                        const float* __restrict__ bias_i, const float* __restrict__ bias_t,
                        float* __restrict__ out) {
    if (blockIdx.x >= FIN_BLOCKS) {
        int i = (blockIdx.x - FIN_BLOCKS) * 256 + threadIdx.x;
        if (i < NN) g_count[i] = 0;
        return;
    }
    int warp = (blockIdx.x * blockDim.x + threadIdx.x) >> 5;
    int lane = threadIdx.x & 31;
    int g = warp / BATCH;
    int i = warp - g * BATCH;
    int idx = (g == 0) ? __ldg(&uidx[i]) : (g == 1) ? __ldg(&pidx[i]) : __ldg(&nidx[i]);
    int row = (g == 0) ? idx : (N_USERS + idx);

    // ---- layer-3 propagation computed on the fly from F2 (fp32 accum) ----
    int s = g_rowstart[row];
    int e = g_rowstart[row + 1];
    float a0 = 0.f, a1 = 0.f, i0 = 0.f, i1 = 0.f, t0 = 0.f, t1 = 0.f;
    for (int k = s; k < e; k++) {
        int2  ed = __ldg(&g_edge[k]);
        float v  = __int_as_float(ed.y);
        const __half2* xr = (const __half2*)(g_F2 + (size_t)ed.x * FDIM);
        float2 f0 = __half22float2(xr[lane]);
        float2 f1 = __half22float2(xr[32 + lane]);
        float2 f2 = __half22float2(xr[64 + lane]);
        a0 += v * f0.x; a1 += v * f0.y;
        i0 += v * f1.x; i1 += v * f1.y;
        t0 += v * f2.x; t1 += v * f2.y;
    }
    int doff = lane * 2;
    float2 bi = *(const float2*)(bias_i + doff);
    float2 bt = *(const float2*)(bias_t + doff);
    i0 += bi.x; i1 += bi.y;
    t0 += bt.x; t1 += bt.y;

    // ---- sum layers 0..2 (stored) + layer 3 (registers), mean ----
    size_t base = (size_t)row * FDIM;
    const __half2* r0 = (const __half2*)(g_F0 + base);
    const __half2* r1 = (const __half2*)(g_F1 + base);
    const __half2* r2 = (const __half2*)(g_F2 + base);

    const float inv = 0.25f;
    float2 me, mi, mt;
    {
        float2 a = __half22float2(r0[lane]), b = __half22float2(r1[lane]);
        float2 c = __half22float2(r2[lane]);
        me.x = (a.x + b.x + c.x + a0) * inv;  me.y = (a.y + b.y + c.y + a1) * inv;
    }
    {
        float2 a = __half22float2(r0[32 + lane]), b = __half22float2(r1[32 + lane]);
        float2 c = __half22float2(r2[32 + lane]);
        mi.x = (a.x + b.x + c.x + i0) * inv;  mi.y = (a.y + b.y + c.y + i1) * inv;
    }
    {
        float2 a = __half22float2(r0[64 + lane]), b = __half22float2(r1[64 + lane]);
        float2 c = __half22float2(r2[64 + lane]);
        mt.x = (a.x + b.x + c.x + t0) * inv;  mt.y = (a.y + b.y + c.y + t1) * inv;
    }

    float sqi = mi.x * mi.x + mi.y * mi.y;
    float sqt = mt.x * mt.x + mt.y * mt.y;
    #pragma unroll
    for (int off = 16; off > 0; off >>= 1) {
        sqi += __shfl_xor_sync(0xFFFFFFFFu, sqi, off);
        sqt += __shfl_xor_sync(0xFFFFFFFFu, sqt, off);
    }
    float si = CAT_RATE / fmaxf(sqrtf(sqi), 1e-12f);
    float st = CAT_RATE / fmaxf(sqrtf(sqt), 1e-12f);

    float2 oe;
    oe.x = me.x + si * mi.x + st * mt.x;
    oe.y = me.y + si * mi.y + st * mt.y;

    size_t slot = (size_t)i * EMBED + doff;
    size_t grp  = (size_t)BATCH * EMBED;
    *(float2*)(out + (size_t)g * grp + slot)       = oe;
    *(float2*)(out + (size_t)(3 + g) * grp + slot) = mi;
    *(float2*)(out + (size_t)(6 + g) * grp + slot) = mt;
}

// ---------------- launch ------------------------------------------------------
extern "C" void kernel_launch(void* const* d_in, const int* in_sizes, int n_in,
                              void* d_out, int out_size) {
    const int*   uidx   = (const int*)  d_in[0];
    const int*   pidx   = (const int*)  d_in[1];
    const int*   nidx   = (const int*)  d_in[2];
    const int*   arows  = (const int*)  d_in[3];
    const int*   acols  = (const int*)  d_in[4];
    const float* avals  = (const float*)d_in[5];
    const float* E0     = (const float*)d_in[6];
    const float* Wimg   = (const float*)d_in[7];
    const float* Bimg   = (const float*)d_in[8];
    const float* Wtxt   = (const float*)d_in[9];
    const float* Btxt   = (const float*)d_in[10];
    float* out = (float*)d_out;

    __half *F0, *F1, *F2;
    cudaGetSymbolAddress((void**)&F0, g_F0);
    cudaGetSymbolAddress((void**)&F1, g_F1);
    cudaGetSymbolAddress((void**)&F2, g_F2);

    // fused histogram + feature init (independent work, one grid)
    k_fused_hist_init<<<NB_FUSED, 256>>>(arows, E0, Wimg, Wtxt);

    // CSR offsets + edge scatter
    k_scan_p1<<<SCAN_NB, SCAN_T>>>();
    k_scan_p3<<<SCAN_NB, SCAN_T>>>();
    k_scatter<<<(NEDGES + 255) / 256, 256>>>(arows, acols, avals);

    // 2 full propagation layers (layer 3 fused into k_final)
    int spmm_blocks = (NN * 32 + 255) / 256;
    k_spmm<<<spmm_blocks, 256>>>(F0, F1, Bimg, Btxt);
    k_spmm<<<spmm_blocks, 256>>>(F1, F2, Bimg, Btxt);

    // final: on-the-fly layer 3 + sum/mean/normalize/gather (+ g_count reset)
    k_final<<<FIN_BLOCKS + ZERO_BLOCKS, 256>>>(uidx, pidx, nidx, Bimg, Btxt, out);
}